// round 2
// baseline (speedup 1.0000x reference)
#include <cuda_runtime.h>
#include <cstdint>
#include <cstddef>

#define B_ROWS 8192
#define KDIM   4096
#define KW     128              // 4096 bits / 32
#define NMAX   4096
#define RCHUNK 32
#define ROWS_PER_CHUNK (B_ROWS / RCHUNK)   // 256

// ---------------- scratch (device globals; no runtime allocation) ----------------
__device__ unsigned   g_A0[(size_t)B_ROWS * KW];        // 4 MB  packed activations ping
__device__ unsigned   g_A1[(size_t)B_ROWS * KW];        // 4 MB  packed activations pong
__device__ unsigned   g_Wb[(size_t)NMAX * KW];          // 2 MB  packed weights (per layer)
__device__ int        g_S [(size_t)B_ROWS * NMAX];      // 134 MB pre-BN integer activations
__device__ long long  g_psum  [RCHUNK * NMAX];
__device__ long long  g_psumsq[RCHUNK * NMAX];
__device__ int        g_pmax  [RCHUNK * NMAX];
__device__ int        g_pmin  [RCHUNK * NMAX];
__device__ float      g_mu[NMAX];
__device__ float      g_scale[NMAX];
__device__ float      g_amax[NMAX];
__device__ float      g_pexp[RCHUNK * 1024];
__device__ float      g_dinv[1024];

// ---------------- 1) binarize+pack x (bit k of word = (x-0.5 >= 0)) ----------------
__global__ void pack_x_kernel(const float* __restrict__ x) {
    unsigned idx = blockIdx.x * 256u + threadIdx.x;          // over B*K elements (exact)
    float v = x[idx];
    unsigned m = __ballot_sync(0xFFFFFFFFu, (v - 0.5f) >= 0.0f);
    if ((threadIdx.x & 31u) == 0u) g_A0[idx >> 5] = m;
}

// ---------------- 2) binarize+pack W, column-major bits: g_Wb[j][w] ----------------
__global__ void pack_w_kernel(const float* __restrict__ W, int N) {
    int j = blockIdx.x * 256 + threadIdx.x;                  // output column
    int w = blockIdx.y;                                      // k-word 0..127
    const float* p = W + (size_t)w * 32 * N + j;
    unsigned m = 0;
    #pragma unroll
    for (int b = 0; b < 32; ++b)
        if (p[(size_t)b * N] >= 0.0f) m |= (1u << b);
    g_Wb[(size_t)j * KW + w] = m;
}

// ---------------- 3) XNOR-popcount GEMM: S[i][j] = K - 2*popc_mismatch ----------------
__global__ __launch_bounds__(256, 2)
void gemm_popc_kernel(int which_a, int N) {
    const unsigned* __restrict__ A = which_a ? g_A1 : g_A0;
    __shared__ __align__(16) unsigned sA[16][132];           // [kword][row], padded
    __shared__ __align__(16) unsigned sB[16][132];           // [kword][col], padded
    int tx = threadIdx.x & 15;
    int ty = threadIdx.x >> 4;
    int rowBlk = blockIdx.y * 128;
    int colBlk = blockIdx.x * 128;

    int acc[8][8];
    #pragma unroll
    for (int m = 0; m < 8; ++m)
        #pragma unroll
        for (int n = 0; n < 8; ++n) acc[m][n] = 0;

    for (int kw0 = 0; kw0 < KW; kw0 += 16) {
        #pragma unroll
        for (int t = 0; t < 8; ++t) {
            int idx = threadIdx.x + t * 256;
            int r  = idx >> 4;
            int kk = idx & 15;
            sA[kk][r] = A[(size_t)(rowBlk + r) * KW + kw0 + kk];
            sB[kk][r] = g_Wb[(size_t)(colBlk + r) * KW + kw0 + kk];
        }
        __syncthreads();
        #pragma unroll 4
        for (int kk = 0; kk < 16; ++kk) {
            unsigned a[8], b[8];
            uint4 t0 = *(const uint4*)&sA[kk][ty * 4];
            uint4 t1 = *(const uint4*)&sA[kk][64 + ty * 4];
            a[0]=t0.x; a[1]=t0.y; a[2]=t0.z; a[3]=t0.w;
            a[4]=t1.x; a[5]=t1.y; a[6]=t1.z; a[7]=t1.w;
            uint4 u0 = *(const uint4*)&sB[kk][tx * 4];
            uint4 u1 = *(const uint4*)&sB[kk][64 + tx * 4];
            b[0]=u0.x; b[1]=u0.y; b[2]=u0.z; b[3]=u0.w;
            b[4]=u1.x; b[5]=u1.y; b[6]=u1.z; b[7]=u1.w;
            #pragma unroll
            for (int m = 0; m < 8; ++m)
                #pragma unroll
                for (int n = 0; n < 8; ++n)
                    acc[m][n] += __popc(a[m] ^ b[n]);
        }
        __syncthreads();
    }
    #pragma unroll
    for (int m = 0; m < 8; ++m) {
        int row = rowBlk + ((m < 4) ? (ty * 4 + m) : (64 + ty * 4 + m - 4));
        #pragma unroll
        for (int n = 0; n < 8; ++n) {
            int col = colBlk + ((n < 4) ? (tx * 4 + n) : (64 + tx * 4 + n - 4));
            g_S[(size_t)row * N + col] = KDIM - 2 * acc[m][n];
        }
    }
}

// ---------------- 4) per-column partial stats over row chunks ----------------
__global__ void colstats_kernel(int N) {
    int j = blockIdx.x * 256 + threadIdx.x;
    int c = blockIdx.y;
    const int* p = g_S + (size_t)c * ROWS_PER_CHUNK * N + j;
    long long sum = 0, ss = 0;
    int mx = -2147483647, mn = 2147483647;
    #pragma unroll 8
    for (int r = 0; r < ROWS_PER_CHUNK; ++r) {
        int v = p[(size_t)r * N];
        sum += v;
        ss  += (long long)(v * v);
        mx = max(mx, v);
        mn = min(mn, v);
    }
    g_psum  [c * N + j] = sum;
    g_psumsq[c * N + j] = ss;
    g_pmax  [c * N + j] = mx;
    g_pmin  [c * N + j] = mn;
}

// ---------------- 5) finalize mu/scale (+ column max of post-BN value) ----------------
__global__ void finalize_stats_kernel(const float* __restrict__ gamma,
                                      const float* __restrict__ beta,
                                      int layer, int N) {
    int j = blockIdx.x * 256 + threadIdx.x;
    long long sum = 0, ss = 0;
    int mx = -2147483647, mn = 2147483647;
    #pragma unroll
    for (int c = 0; c < RCHUNK; ++c) {
        sum += g_psum  [c * N + j];
        ss  += g_psumsq[c * N + j];
        mx = max(mx, g_pmax[c * N + j]);
        mn = min(mn, g_pmin[c * N + j]);
    }
    double m   = (double)sum / (double)B_ROWS;
    double var = (double)ss  / (double)B_ROWS - m * m;
    float g  = gamma[layer];
    float be = beta[layer];
    float sc = g * rsqrtf((float)var + 1e-5f);
    g_mu[j]    = (float)m;
    g_scale[j] = sc;
    float hi = ((float)mx - (float)m) * sc + be;
    float lo = ((float)mn - (float)m) * sc + be;
    g_amax[j] = fmaxf(hi, lo);
}

// ---------------- 6) BN + binarize + repack into next-layer activation bits ----------------
__global__ void bn_bin_pack_kernel(const float* __restrict__ beta,
                                   int layer, int which_out, int N) {
    unsigned idx = blockIdx.x * 256u + threadIdx.x;          // over B*N (exact)
    int j = idx & (unsigned)(N - 1);                         // N is a power of two
    float a = ((float)g_S[idx] - g_mu[j]) * g_scale[j] + beta[layer];
    unsigned m = __ballot_sync(0xFFFFFFFFu, a >= 0.0f);
    unsigned* out = which_out ? g_A1 : g_A0;
    if ((threadIdx.x & 31u) == 0u) out[idx >> 5] = m;
}

// ---------------- 7) softmax over batch: chunked exp-sum partials ----------------
__global__ void sumexp_kernel(const float* __restrict__ beta, int N) {
    int j = blockIdx.x * 256 + threadIdx.x;
    int c = blockIdx.y;
    float m  = g_mu[j];
    float sc = g_scale[j];
    float be = beta[2];
    float ax = g_amax[j];
    const int* p = g_S + (size_t)c * ROWS_PER_CHUNK * N + j;
    float sum = 0.0f;
    #pragma unroll 8
    for (int r = 0; r < ROWS_PER_CHUNK; ++r)
        sum += __expf(((float)p[(size_t)r * N] - m) * sc + be - ax);
    g_pexp[c * N + j] = sum;
}

__global__ void finalize_denom_kernel(int N) {
    int j = blockIdx.x * 256 + threadIdx.x;
    float s = 0.0f;
    #pragma unroll
    for (int c = 0; c < RCHUNK; ++c) s += g_pexp[c * N + j];
    g_dinv[j] = 1.0f / s;
}

__global__ void write_out_kernel(const float* __restrict__ beta,
                                 float* __restrict__ out, int N) {
    unsigned idx = blockIdx.x * 256u + threadIdx.x;          // over B*N (exact)
    int j = idx & (unsigned)(N - 1);
    float a = ((float)g_S[idx] - g_mu[j]) * g_scale[j] + beta[2] - g_amax[j];
    out[idx] = __expf(a) * g_dinv[j];
}

// ---------------- driver ----------------
extern "C" void kernel_launch(void* const* d_in, const int* in_sizes, int n_in,
                              void* d_out, int out_size) {
    (void)in_sizes; (void)n_in; (void)out_size;
    const float* x     = (const float*)d_in[0];
    const float* Ws[3] = {(const float*)d_in[1], (const float*)d_in[2], (const float*)d_in[3]};
    const float* gamma = (const float*)d_in[4];
    const float* beta  = (const float*)d_in[5];
    float* out = (float*)d_out;
    const int Ns[3] = {4096, 4096, 1024};

    pack_x_kernel<<<(B_ROWS * KDIM) / 256, 256>>>(x);

    int cur = 0;
    for (int k = 0; k < 3; ++k) {
        int N = Ns[k];
        pack_w_kernel<<<dim3(N / 256, KW), 256>>>(Ws[k], N);
        gemm_popc_kernel<<<dim3(N / 128, B_ROWS / 128), 256>>>(cur, N);
        colstats_kernel<<<dim3(N / 256, RCHUNK), 256>>>(N);
        finalize_stats_kernel<<<N / 256, 256>>>(gamma, beta, k, N);
        if (k < 2) {
            bn_bin_pack_kernel<<<(B_ROWS * N) / 256, 256>>>(beta, k, cur ^ 1, N);
            cur ^= 1;
        } else {
            sumexp_kernel<<<dim3(N / 256, RCHUNK), 256>>>(beta, N);
            finalize_denom_kernel<<<N / 256, 256>>>(N);
            write_out_kernel<<<(B_ROWS * N) / 256, 256>>>(beta, out, N);
        }
    }
}